// round 16
// baseline (speedup 1.0000x reference)
#include <cuda_runtime.h>
#include <cstdint>

// Problem constants (fixed by reference setup_inputs)
#define NS     16
#define NP     2048
#define DIM    64
#define KNN    16
#define BLOCK  128
#define QT     128             // queries per CTA
#define CT     64              // candidates per tile
#define NTILES (NP / CT)       // 32
#define BUFS   8               // ring-buffer slots per thread
#define NTOT   (NS * NP * KNN) // 524288

// smem layout (bytes)
#define OFF_Q    0u            // Qs: 128 rows x 256 B (swizzled)      = 32768
#define OFF_C    32768u        // Cs: 64 rows x 256 B (swizzled)       = 16384
#define OFF_D    49152u        // Ds: 128 rows x 260 B (65-f stride)   = 33280
#define DSTR     260u
#define OFF_X2   82432u        // x2 of all 2048 points               =  8192
#define OFF_RING 90624u        // 128 threads x 8 slots x 8 B          =  8192
#define SM_TOTAL 98816

typedef unsigned long long ull;
#define INFKEY 0x7f800000ffffffffULL   // (+inf dist bits, max idx)

// ---- packed f32x2 helpers (sm_103a) ------------------------------------
__device__ __forceinline__ ull fma2(ull a, ull b, ull c) {
    ull d; asm("fma.rn.f32x2 %0, %1, %2, %3;" : "=l"(d) : "l"(a), "l"(b), "l"(c)); return d;
}
__device__ __forceinline__ void unpk2(float& lo, float& hi, ull v) {
    asm("mov.b64 {%0, %1}, %2;" : "=f"(lo), "=f"(hi) : "l"(v));
}
__device__ __forceinline__ ull lds64(unsigned a) {
    ull v; asm volatile("ld.shared.b64 %0, [%1];" : "=l"(v) : "r"(a)); return v;
}
__device__ __forceinline__ float lds32f(unsigned a) {
    float v; asm volatile("ld.shared.f32 %0, [%1];" : "=f"(v) : "r"(a)); return v;
}
__device__ __forceinline__ void sts32f(unsigned a, float v) {
    asm volatile("st.shared.f32 [%0], %1;" :: "r"(a), "f"(v) : "memory");
}
__device__ __forceinline__ void sts128(unsigned a, float4 v) {
    asm volatile("st.shared.v4.b32 [%0], {%1, %2, %3, %4};"
                 :: "r"(a), "f"(v.x), "f"(v.y), "f"(v.z), "f"(v.w) : "memory");
}

// Sorted-ascending insert of a composite key (dist_bits<<32 | idx).
// Lexicographic order == top_k value-then-lowest-index (validated in R10).
__device__ __forceinline__ void insert_key(ull (&kd)[KNN], ull key) {
    bool pk = key < kd[KNN - 1];
#pragma unroll
    for (int k = KNN - 1; k >= 1; --k) {
        bool pk1 = key < kd[k - 1];
        kd[k] = pk ? (pk1 ? kd[k - 1] : key) : kd[k];
        pk = pk1;
    }
    if (pk) kd[0] = key;
}

__device__ __forceinline__ void flush_ring(ull (&kd)[KNN], unsigned ringb,
                                           int& cnt, float& thr) {
    for (int u = 0; u < cnt; ++u) {
        float fd; int fi;
        asm volatile("ld.shared.v2.b32 {%0, %1}, [%2];"
                     : "=f"(fd), "=r"(fi)
                     : "r"(ringb + (unsigned)(u * BLOCK * 8)));
        ull key = ((ull)__float_as_uint(fd) << 32) | (unsigned)fi;
        if (key < kd[KNN - 1]) insert_key(kd, key);   // exact stale-skip
    }
    cnt = 0;
    thr = __uint_as_float((unsigned)(kd[KNN - 1] >> 32));
}

__global__ void __launch_bounds__(BLOCK, 2)
knn_kernel(const float* __restrict__ h, float* __restrict__ out, int write_edges) {
    extern __shared__ __align__(16) char dsm[];
    const unsigned S = (unsigned)__cvta_generic_to_shared(dsm);

    const int tid  = threadIdx.x;
    const int b    = blockIdx.x >> 4;
    const int qblk = (blockIdx.x & 15) * QT;
    const float* hb = h + (size_t)b * NP * DIM;

    // ---- squared norms of ALL 2048 points of this sample ----
    for (int i = 0; i < 16; i++) {
        int r = i * BLOCK + tid;
        const float4* rp = (const float4*)(hb + (size_t)r * DIM);
        float s = 0.0f;
#pragma unroll
        for (int j = 0; j < 16; j++) {
            float4 v = rp[j];
            s = fmaf(v.x, v.x, s); s = fmaf(v.y, v.y, s);
            s = fmaf(v.z, v.z, s); s = fmaf(v.w, v.w, s);
        }
        sts32f(S + OFF_X2 + (unsigned)r * 4, s);
    }

    // ---- load Q tile (128 rows) with 16B-chunk XOR swizzle ----
    for (int i = 0; i < 16; i++) {
        int idx = i * BLOCK + tid;
        int row = idx >> 4, c16 = idx & 15;
        float4 v = ((const float4*)(hb + (size_t)(qblk + row) * DIM))[c16];
        sts128(S + OFF_Q + (unsigned)row * 256 +
               (unsigned)((c16 ^ ((row >> 3) & 7)) << 4), v);
    }
    __syncthreads();

    // ---- per-thread state ----
    ull kd[KNN];
#pragma unroll
    for (int k = 0; k < KNN; k++) kd[k] = INFKEY;
    float thr = __int_as_float(0x7f800000);
    int cnt = 0;
    const unsigned ringb = S + OFF_RING + (unsigned)tid * 8;

    const int qg = tid >> 3, cg = tid & 7;
    const unsigned qbase = S + OFF_Q + (unsigned)(qg * 8) * 256;
    const unsigned cbase = S + OFF_C;
    const unsigned qx = (unsigned)(qg & 7), cx = (unsigned)cg;
    const unsigned dsel = S + OFF_D + (unsigned)tid * DSTR;

    float x2qv[8];
#pragma unroll
    for (int qi = 0; qi < 8; qi++)
        x2qv[qi] = lds32f(S + OFF_X2 + (unsigned)(qblk + qg * 8 + qi) * 4);

    for (int tt = 0; tt < NTILES; tt++) {
        __syncthreads();   // Cs / Ds free from previous tile
        // ---- load C tile (64 rows) swizzled ----
        for (int i = 0; i < 8; i++) {
            int idx = i * BLOCK + tid;
            int row = idx >> 4, c16 = idx & 15;
            float4 v = ((const float4*)(hb + (size_t)(tt * CT + row) * DIM))[c16];
            sts128(S + OFF_C + (unsigned)row * 256 +
                   (unsigned)((c16 ^ (row >> 3)) << 4), v);
        }
        __syncthreads();

        float x2cv[8];
#pragma unroll
        for (int ci = 0; ci < 8; ci++)
            x2cv[ci] = lds32f(S + OFF_X2 + (unsigned)(tt * CT + cg * 8 + ci) * 4);

        // ---- GEMM: 8q x 8c micro-tile, k-packed f32x2 accumulators ----
        ull acc[64];
#pragma unroll
        for (int a = 0; a < 64; a++) acc[a] = 0ull;

#pragma unroll 4
        for (int k = 0; k < 32; k++) {     // 2 dims per step
            unsigned oq = (unsigned)((((k >> 1) ^ qx) << 4) | ((k & 1) << 3));
            unsigned oc = (unsigned)((((k >> 1) ^ cx) << 4) | ((k & 1) << 3));
            ull qf[8], cf[8];
#pragma unroll
            for (int qi = 0; qi < 8; qi++) qf[qi] = lds64(qbase + qi * 256 + oq);
#pragma unroll
            for (int ci = 0; ci < 8; ci++)
                cf[ci] = lds64(cbase + (unsigned)(cg * 8 + ci) * 256 + oc);
#pragma unroll
            for (int qi = 0; qi < 8; qi++)
#pragma unroll
                for (int ci = 0; ci < 8; ci++)
                    acc[qi * 8 + ci] = fma2(qf[qi], cf[ci], acc[qi * 8 + ci]);
        }

        // ---- epilogue: distances -> Ds ----
        // Store candidate column (cg*8+ci) at PERMUTED position (ci*8+cg):
        // bank = (8qg + 65qi + 8ci + cg) mod 32 -> 32 distinct lanes, no
        // conflicts (unpermuted layout was 8-way conflicted).
#pragma unroll
        for (int qi = 0; qi < 8; qi++) {
#pragma unroll
            for (int ci = 0; ci < 8; ci++) {
                float lo, hi; unpk2(lo, hi, acc[qi * 8 + ci]);
                float d = fmaf(-2.0f, lo + hi, x2qv[qi] + x2cv[ci]);
                d = fmaxf(d, 0.0f);
                sts32f(S + OFF_D + (unsigned)(qg * 8 + qi) * DSTR +
                       (unsigned)(ci * 8 + cg) * 4, d);
            }
        }
        __syncthreads();

        // ---- selection: thread t owns query t ----
        // Position j holds candidate column (j&7)*8 + (j>>3) (store permute).
        const int gb = tt * CT;
        for (int j = 0; j < CT; j++) {
            float d = lds32f(dsel + (unsigned)j * 4);
            if (d < thr) {
                int cand = gb + ((j & 7) << 3) + (j >> 3);
                asm volatile("st.shared.v2.b32 [%0], {%1, %2};"
                             :: "r"(ringb + (unsigned)(cnt * (BLOCK * 8))),
                                "f"(d), "r"(cand) : "memory");
                cnt++;
            }
            if (__ballot_sync(0xffffffffu, cnt >= BUFS))
                flush_ring(kd, ringb, cnt, thr);
        }
    }
    flush_ring(kd, ringb, cnt, thr);

    // ---- write output: [knn_dist | dst | src] ----
    const int gq = b * NP + qblk + tid;
    const size_t o = (size_t)gq * KNN;
#pragma unroll
    for (int k = 0; k < KNN; k++) {
        out[o + k] = __uint_as_float((unsigned)(kd[k] >> 32));
        if (write_edges) {
            out[(size_t)NTOT + o + k] =
                (float)((int)(kd[k] & 0xffffffffu) + b * NP);
            out[(size_t)2 * NTOT + o + k] = (float)gq;
        }
    }
}

extern "C" void kernel_launch(void* const* d_in, const int* in_sizes, int n_in,
                              void* d_out, int out_size) {
    const float* h = (const float*)d_in[0];
    int write_edges = (out_size >= 3 * NTOT) ? 1 : 0;
    cudaFuncSetAttribute(knn_kernel,
                         cudaFuncAttributeMaxDynamicSharedMemorySize, SM_TOTAL);
    knn_kernel<<<NS * (NP / QT), BLOCK, SM_TOTAL>>>(h, (float*)d_out, write_edges);
}